// round 1
// baseline (speedup 1.0000x reference)
#include <cuda_runtime.h>

// Problem constants (fixed by reference: B=16, H=128, W=128, C=256, D=C/8=32)
#define WTOK 128      // tokens per group (width)
#define CDIM 256      // channels
#define DDIM 32       // q/k dim
#define NTHR 512

// Shared memory layout (floats):
//   Xs : [128][256]      offset 0       (32768 floats, 128 KB)
//   S  : [128][128]      offset 32768   (16384 floats,  64 KB)
//   QK : [128][65]       offset 49152   ( 8320 floats, 32.5 KB)  (reused as V tile)
#define XS_OFF   0
#define S_OFF    32768
#define QKV_OFF  49152
#define SMEM_FLOATS (49152 + 128*65)
#define SMEM_BYTES  (SMEM_FLOATS * 4)   // 229,888 B <= 232,448 max dyn smem

__global__ __launch_bounds__(NTHR, 1)
void attn_fused_kernel(const float* __restrict__ X,
                       const float* __restrict__ Wq, const float* __restrict__ bq,
                       const float* __restrict__ Wk, const float* __restrict__ bk,
                       const float* __restrict__ Wv, const float* __restrict__ bv,
                       float* __restrict__ out)
{
    extern __shared__ float sm[];
    float* Xs = sm + XS_OFF;    // [128][256]
    float* S  = sm + S_OFF;     // [128][128]
    float* QK = sm + QKV_OFF;   // [128][65] : cols 0..31 = Q, 32..63 = K
    float* Vt = QK;             // reused after scores are computed

    const int t = threadIdx.x;
    const long long g = blockIdx.x;
    const float* Xg = X + g * (long long)(WTOK * CDIM);
    float* Og = out + g * (long long)(WTOK * CDIM);

    // ---------------- Phase 0: load X tile (coalesced float4) ----------------
    {
        const float4* Xg4 = (const float4*)Xg;
        float4* Xs4 = (float4*)Xs;
        #pragma unroll
        for (int i = t; i < WTOK * CDIM / 4; i += NTHR)
            Xs4[i] = Xg4[i];
    }
    __syncthreads();

    // ---------------- Phase 1: QK[r][d] = X @ [Wq|Wk] + bias ----------------
    // thread: d = t&63 (Q for d<32, K for d>=32), row group rg = t>>6 (16 rows each)
    {
        const int d  = t & 63;
        const int rg = t >> 6;
        const float* Wp = (d < 32) ? (Wq + d) : (Wk + (d - 32));
        const float bias = (d < 32) ? bq[d] : bk[d - 32];
        float acc[16];
        #pragma unroll
        for (int i = 0; i < 16; i++) acc[i] = 0.f;
        const float* xrow = Xs + (rg * 16) * CDIM;
        for (int k = 0; k < CDIM; k += 4) {
            const float w0 = Wp[(k + 0) * DDIM];
            const float w1 = Wp[(k + 1) * DDIM];
            const float w2 = Wp[(k + 2) * DDIM];
            const float w3 = Wp[(k + 3) * DDIM];
            #pragma unroll
            for (int i = 0; i < 16; i++) {
                float4 x = *(const float4*)&xrow[i * CDIM + k];
                acc[i] = fmaf(x.x, w0, acc[i]);
                acc[i] = fmaf(x.y, w1, acc[i]);
                acc[i] = fmaf(x.z, w2, acc[i]);
                acc[i] = fmaf(x.w, w3, acc[i]);
            }
        }
        #pragma unroll
        for (int i = 0; i < 16; i++)
            QK[(rg * 16 + i) * 65 + d] = acc[i] + bias;
    }
    __syncthreads();

    // ---------------- Phase 2: S = Q @ K^T ----------------
    // thread: j = t&127 (fixed column, K row cached in regs), i = 4*ib + (t>>7)
    {
        const int j  = t & 127;
        const int i0 = t >> 7;
        float kreg[DDIM];
        #pragma unroll
        for (int d = 0; d < DDIM; d++) kreg[d] = QK[j * 65 + 32 + d];
        for (int ib = 0; ib < 32; ib++) {
            const int i = ib * 4 + i0;
            const float* qrow = QK + i * 65;
            float s = 0.f;
            #pragma unroll
            for (int d = 0; d < DDIM; d++) s = fmaf(qrow[d], kreg[d], s);
            S[i * 128 + j] = s;
        }
    }
    __syncthreads();

    // ---------------- Phase 3: row softmax of S ----------------
    {
        const int warp = t >> 5, lane = t & 31;
        for (int rr = 0; rr < 8; rr++) {
            float* row = S + (warp * 8 + rr) * 128;
            float x0 = row[lane], x1 = row[lane + 32], x2 = row[lane + 64], x3 = row[lane + 96];
            float m = fmaxf(fmaxf(x0, x1), fmaxf(x2, x3));
            #pragma unroll
            for (int o = 16; o > 0; o >>= 1) m = fmaxf(m, __shfl_xor_sync(0xffffffffu, m, o));
            x0 = __expf(x0 - m); x1 = __expf(x1 - m);
            x2 = __expf(x2 - m); x3 = __expf(x3 - m);
            float s = x0 + x1 + x2 + x3;
            #pragma unroll
            for (int o = 16; o > 0; o >>= 1) s += __shfl_xor_sync(0xffffffffu, s, o);
            const float inv = 1.f / s;
            row[lane] = x0 * inv; row[lane + 32] = x1 * inv;
            row[lane + 64] = x2 * inv; row[lane + 96] = x3 * inv;
        }
    }
    __syncthreads();

    // ---------------- Phase 4: per 64-col tile: V = X@Wv, then O = A@V + bv ----
    // Note: softmax rows sum to 1, so bias bv folds directly into the output.
    {
        const int c  = t & 63;
        const int rg = t >> 6;
        for (int jt = 0; jt < 4; jt++) {
            // 4a: Vt[j][c] = sum_k Xs[j][k] * Wv[k][jt*64+c]
            {
                const float* Wp = Wv + jt * 64 + c;
                float acc[16];
                #pragma unroll
                for (int i = 0; i < 16; i++) acc[i] = 0.f;
                const float* xrow = Xs + (rg * 16) * CDIM;
                for (int k = 0; k < CDIM; k += 4) {
                    const float w0 = Wp[(k + 0) * CDIM];
                    const float w1 = Wp[(k + 1) * CDIM];
                    const float w2 = Wp[(k + 2) * CDIM];
                    const float w3 = Wp[(k + 3) * CDIM];
                    #pragma unroll
                    for (int i = 0; i < 16; i++) {
                        float4 x = *(const float4*)&xrow[i * CDIM + k];
                        acc[i] = fmaf(x.x, w0, acc[i]);
                        acc[i] = fmaf(x.y, w1, acc[i]);
                        acc[i] = fmaf(x.z, w2, acc[i]);
                        acc[i] = fmaf(x.w, w3, acc[i]);
                    }
                }
                #pragma unroll
                for (int i = 0; i < 16; i++)
                    Vt[(rg * 16 + i) * 65 + c] = acc[i];
            }
            __syncthreads();
            // 4b: O[i][jt*64+c] = sum_j S[i][j] * Vt[j][c] + bv
            {
                float acc[16];
                #pragma unroll
                for (int i = 0; i < 16; i++) acc[i] = 0.f;
                const float* srow0 = S + (rg * 16) * 128;
                for (int j = 0; j < 128; j += 4) {
                    const float v0 = Vt[(j + 0) * 65 + c];
                    const float v1 = Vt[(j + 1) * 65 + c];
                    const float v2 = Vt[(j + 2) * 65 + c];
                    const float v3 = Vt[(j + 3) * 65 + c];
                    #pragma unroll
                    for (int i = 0; i < 16; i++) {
                        float4 a = *(const float4*)&srow0[i * 128 + j];
                        acc[i] = fmaf(a.x, v0, acc[i]);
                        acc[i] = fmaf(a.y, v1, acc[i]);
                        acc[i] = fmaf(a.z, v2, acc[i]);
                        acc[i] = fmaf(a.w, v3, acc[i]);
                    }
                }
                const float bias = bv[jt * 64 + c];
                #pragma unroll
                for (int i = 0; i < 16; i++)
                    Og[(rg * 16 + i) * CDIM + jt * 64 + c] = acc[i] + bias;
            }
            __syncthreads();
        }
    }
}

extern "C" void kernel_launch(void* const* d_in, const int* in_sizes, int n_in,
                              void* d_out, int out_size)
{
    const float* X  = (const float*)d_in[0];
    const float* Wq = (const float*)d_in[1];
    const float* bq = (const float*)d_in[2];
    const float* Wk = (const float*)d_in[3];
    const float* bk = (const float*)d_in[4];
    const float* Wv = (const float*)d_in[5];
    const float* bv = (const float*)d_in[6];
    float* out = (float*)d_out;

    // number of (b,h) groups = total elems / (W*C)
    const int groups = in_sizes[0] / (WTOK * CDIM);   // 2048

    cudaFuncSetAttribute(attn_fused_kernel,
                         cudaFuncAttributeMaxDynamicSharedMemorySize, SMEM_BYTES);
    attn_fused_kernel<<<groups, NTHR, SMEM_BYTES>>>(X, Wq, bq, Wk, bk, Wv, bv, out);
}

// round 4
// speedup vs baseline: 3.6931x; 3.6931x over previous
#include <cuda_runtime.h>
#include <cuda_bf16.h>
#include <cstdint>

// B=16,H=128 -> 2048 groups; per group X[128,256], D=32.
#define NTHR 256

// ---------------- SMEM layout (bytes) ----------------
#define XSTR    544                  // X row stride (272 bf16 slots)
#define XH_OFF  0                    // X hi [128][XSTR]  = 69,632
#define XL_OFF  69632                // X lo
#define WB0     139264               // weight buffer 0 (34,816)
#define WB1     174080               // weight buffer 1 (34,816)
#define WCHUNK  34816                // chunk image: hi[32][XSTR] + lo[32][XSTR]
#define WLO     17408
#define KH_OFF  174080               // K image hi [128][KSTR] (overlays WB1)
#define KL_OFF  186368               // K image lo
#define KSTR    96
#define VTH_OFF 208896               // V^T chunk hi [32][VSTR]
#define VTL_OFF 218112               // V^T chunk lo
#define VSTR    288
#define SMEM_BYTES 227328

// k-permutation: within each 16-block, pairs (2q,2q+1) and (2q+8,2q+9) are
// contiguous -> one LDS.64 yields a full half A-fragment / B-fragment.
__device__ __forceinline__ int kslot(int k) {
    return (k & ~15) | (((k >> 1) & 3) << 2) | (((k >> 3) & 1) << 1) | (k & 1);
}

// 10 weight-chunk images: 0=Wq, 1=Wk, 2..9=Wv col-chunks of 32 (each [n=32][k=256])
__device__ __align__(16) unsigned char g_wimg[10 * WCHUNK];

// ---------------- helpers ----------------
__device__ __forceinline__ uint32_t smem_u32(const void* p) {
    uint32_t a;
    asm("{ .reg .u64 t; cvta.to.shared.u64 t, %1; cvt.u32.u64 %0, t; }" : "=r"(a) : "l"(p));
    return a;
}
__device__ __forceinline__ void cp16(void* sdst, const void* gsrc) {
    asm volatile("cp.async.cg.shared.global [%0], [%1], 16;"
                 :: "r"(smem_u32(sdst)), "l"(gsrc));
}
#define CP_COMMIT() asm volatile("cp.async.commit_group;" ::: "memory")
#define CP_WAIT0()  asm volatile("cp.async.wait_group 0;" ::: "memory")

__device__ __forceinline__ void mma16816(float* c, uint32_t a0, uint32_t a1,
                                         uint32_t a2, uint32_t a3,
                                         uint32_t b0, uint32_t b1) {
    asm volatile(
        "mma.sync.aligned.m16n8k16.row.col.f32.bf16.bf16.f32 "
        "{%0,%1,%2,%3},{%4,%5,%6,%7},{%8,%9},{%0,%1,%2,%3};"
        : "+f"(c[0]), "+f"(c[1]), "+f"(c[2]), "+f"(c[3])
        : "r"(a0), "r"(a1), "r"(a2), "r"(a3), "r"(b0), "r"(b1));
}
// 3-pass split: C += Ah*Bh + Ah*Bl + Al*Bh   (A args as uint2: .x=a0/a1, .y=a2/a3)
__device__ __forceinline__ void mma3(float* c, uint2 ah0, uint2 ah1,
                                     uint2 al0, uint2 al1, uint2 bh, uint2 bl) {
    mma16816(c, ah0.x, ah1.x, ah0.y, ah1.y, bh.x, bh.y);
    mma16816(c, ah0.x, ah1.x, ah0.y, ah1.y, bl.x, bl.y);
    mma16816(c, al0.x, al1.x, al0.y, al1.y, bh.x, bh.y);
}

__device__ __forceinline__ uint32_t pack_hi(float x, float y) {
    __nv_bfloat162 p = __floats2bfloat162_rn(x, y);
    return *reinterpret_cast<uint32_t*>(&p);
}
__device__ __forceinline__ uint32_t pack_lo(float x, float y) {
    float xh = __bfloat162float(__float2bfloat16(x));
    float yh = __bfloat162float(__float2bfloat16(y));
    __nv_bfloat162 p = __floats2bfloat162_rn(x - xh, y - yh);
    return *reinterpret_cast<uint32_t*>(&p);
}

// =============== prep: weights -> bf16 hi/lo SMEM-image chunks ===============
__global__ void prep_weights(const float* __restrict__ Wq, const float* __restrict__ Wk,
                             const float* __restrict__ Wv) {
    int idx = blockIdx.x * 256 + threadIdx.x;   // 10*32*256 = 81920
    int chunk = idx >> 13;
    int n = (idx >> 8) & 31;
    int k = idx & 255;
    float w;
    if (chunk == 0)      w = Wq[k * 32 + n];
    else if (chunk == 1) w = Wk[k * 32 + n];
    else                 w = Wv[k * 256 + (chunk - 2) * 32 + n];
    __nv_bfloat16 h = __float2bfloat16(w);
    __nv_bfloat16 l = __float2bfloat16(w - __bfloat162float(h));
    unsigned off = (unsigned)chunk * WCHUNK + (unsigned)n * XSTR + (unsigned)kslot(k) * 2;
    *(__nv_bfloat16*)(g_wimg + off)       = h;
    *(__nv_bfloat16*)(g_wimg + off + WLO) = l;
}

// =============== main: one CTA per (b,h) group ===============
__global__ __launch_bounds__(NTHR, 1)
void attn_mma_kernel(const float* __restrict__ X,
                     const float* __restrict__ bq, const float* __restrict__ bk,
                     const float* __restrict__ bv, float* __restrict__ out) {
    extern __shared__ unsigned char sm[];
    const int t = threadIdx.x, w = t >> 5, lane = t & 31;
    const int q = lane & 3, lq = lane >> 2;
    const int R = w * 16;
    const long long g = blockIdx.x;
    const float* Xg = X + g * 32768LL;
    float* Og = out + g * 32768LL;

    // prefetch Wq -> WB0, Wk -> WB1
    for (int i = t; i < WCHUNK / 16; i += NTHR) cp16(sm + WB0 + i * 16, g_wimg + i * 16);
    for (int i = t; i < WCHUNK / 16; i += NTHR) cp16(sm + WB1 + i * 16, g_wimg + WCHUNK + i * 16);
    CP_COMMIT();

    // X load + bf16 hi/lo split into permuted layout
    {
        const float4* X4 = (const float4*)Xg;
        for (int i = t; i < 8192; i += NTHR) {
            int row = i >> 6, k0 = (i & 63) * 4;
            float4 f = X4[i];
            int s0 = kslot(k0), s1 = kslot(k0 + 2);
            unsigned b = (unsigned)row * XSTR;
            *(uint32_t*)(sm + XH_OFF + b + s0 * 2) = pack_hi(f.x, f.y);
            *(uint32_t*)(sm + XH_OFF + b + s1 * 2) = pack_hi(f.z, f.w);
            *(uint32_t*)(sm + XL_OFF + b + s0 * 2) = pack_lo(f.x, f.y);
            *(uint32_t*)(sm + XL_OFF + b + s1 * 2) = pack_lo(f.z, f.w);
        }
    }
    CP_WAIT0();
    __syncthreads();

    const unsigned char* XH0 = sm + XH_OFF + (unsigned)(R + lq) * XSTR;
    const unsigned char* XH1 = XH0 + 8 * XSTR;
    const unsigned char* XL0 = sm + XL_OFF + (unsigned)(R + lq) * XSTR;
    const unsigned char* XL1 = XL0 + 8 * XSTR;

    // ---------------- Q projection ----------------
    float Cq[4][4];
    #pragma unroll
    for (int n = 0; n < 4; n++) { Cq[n][0] = Cq[n][1] = Cq[n][2] = Cq[n][3] = 0.f; }
    #pragma unroll 4
    for (int kt = 0; kt < 16; kt++) {
        unsigned ko = kt * 32 + q * 8;
        uint2 ah0 = *(const uint2*)(XH0 + ko), ah1 = *(const uint2*)(XH1 + ko);
        uint2 al0 = *(const uint2*)(XL0 + ko), al1 = *(const uint2*)(XL1 + ko);
        #pragma unroll
        for (int nt = 0; nt < 4; nt++) {
            const unsigned char* B = sm + WB0 + (unsigned)(nt * 8 + lq) * XSTR + ko;
            mma3(Cq[nt], ah0, ah1, al0, al1, *(const uint2*)B, *(const uint2*)(B + WLO));
        }
    }
    // +bq, repack into scores A-fragments
    uint32_t qh[2][4], ql[2][4];
    #pragma unroll
    for (int nt = 0; nt < 4; nt++) {
        float2 bb = *(const float2*)(bq + nt * 8 + 2 * q);
        Cq[nt][0] += bb.x; Cq[nt][1] += bb.y; Cq[nt][2] += bb.x; Cq[nt][3] += bb.y;
    }
    #pragma unroll
    for (int kt = 0; kt < 2; kt++) {
        qh[kt][0] = pack_hi(Cq[2*kt][0],   Cq[2*kt][1]);
        qh[kt][1] = pack_hi(Cq[2*kt][2],   Cq[2*kt][3]);
        qh[kt][2] = pack_hi(Cq[2*kt+1][0], Cq[2*kt+1][1]);
        qh[kt][3] = pack_hi(Cq[2*kt+1][2], Cq[2*kt+1][3]);
        ql[kt][0] = pack_lo(Cq[2*kt][0],   Cq[2*kt][1]);
        ql[kt][1] = pack_lo(Cq[2*kt][2],   Cq[2*kt][3]);
        ql[kt][2] = pack_lo(Cq[2*kt+1][0], Cq[2*kt+1][1]);
        ql[kt][3] = pack_lo(Cq[2*kt+1][2], Cq[2*kt+1][3]);
    }

    // ---------------- K projection ----------------
    float Ck[4][4];
    #pragma unroll
    for (int n = 0; n < 4; n++) { Ck[n][0] = Ck[n][1] = Ck[n][2] = Ck[n][3] = 0.f; }
    #pragma unroll 4
    for (int kt = 0; kt < 16; kt++) {
        unsigned ko = kt * 32 + q * 8;
        uint2 ah0 = *(const uint2*)(XH0 + ko), ah1 = *(const uint2*)(XH1 + ko);
        uint2 al0 = *(const uint2*)(XL0 + ko), al1 = *(const uint2*)(XL1 + ko);
        #pragma unroll
        for (int nt = 0; nt < 4; nt++) {
            const unsigned char* B = sm + WB1 + (unsigned)(nt * 8 + lq) * XSTR + ko;
            mma3(Ck[nt], ah0, ah1, al0, al1, *(const uint2*)B, *(const uint2*)(B + WLO));
        }
    }
    __syncthreads();   // all warps done reading WB0/WB1 as weights

    // prefetch Wv chunk 0 -> WB0 (overlaps K-image write + scores)
    for (int i = t; i < WCHUNK / 16; i += NTHR) cp16(sm + WB0 + i * 16, g_wimg + 2 * WCHUNK + i * 16);
    CP_COMMIT();

    // write K image (+bk) into WB1 region, split hi/lo
    #pragma unroll
    for (int nt = 0; nt < 4; nt++) {
        float2 bb = *(const float2*)(bk + nt * 8 + 2 * q);
        float c0 = Ck[nt][0] + bb.x, c1 = Ck[nt][1] + bb.y;
        float c2 = Ck[nt][2] + bb.x, c3 = Ck[nt][3] + bb.y;
        int p = kslot(nt * 8 + 2 * q) * 2;
        unsigned o0 = (unsigned)(R + lq) * KSTR + p;
        unsigned o1 = (unsigned)(R + lq + 8) * KSTR + p;
        *(uint32_t*)(sm + KH_OFF + o0) = pack_hi(c0, c1);
        *(uint32_t*)(sm + KH_OFF + o1) = pack_hi(c2, c3);
        *(uint32_t*)(sm + KL_OFF + o0) = pack_lo(c0, c1);
        *(uint32_t*)(sm + KL_OFF + o1) = pack_lo(c2, c3);
    }
    __syncthreads();

    // ---------------- scores S = Q @ K^T ----------------
    float Cs[16][4];
    #pragma unroll
    for (int n = 0; n < 16; n++) { Cs[n][0] = Cs[n][1] = Cs[n][2] = Cs[n][3] = 0.f; }
    #pragma unroll 4
    for (int nt = 0; nt < 16; nt++) {
        const unsigned char* Kp = sm + KH_OFF + (unsigned)(nt * 8 + lq) * KSTR;
        #pragma unroll
        for (int kt = 0; kt < 2; kt++) {
            unsigned ko = kt * 32 + q * 8;
            uint2 bh = *(const uint2*)(Kp + ko);
            uint2 bl = *(const uint2*)(Kp + (KL_OFF - KH_OFF) + ko);
            mma16816(Cs[nt], qh[kt][0], qh[kt][1], qh[kt][2], qh[kt][3], bh.x, bh.y);
            mma16816(Cs[nt], qh[kt][0], qh[kt][1], qh[kt][2], qh[kt][3], bl.x, bl.y);
            mma16816(Cs[nt], ql[kt][0], ql[kt][1], ql[kt][2], ql[kt][3], bh.x, bh.y);
        }
    }

    // ---------------- softmax (registers + quad shuffles) ----------------
    {
        float m0 = -1e30f, m1 = -1e30f;
        #pragma unroll
        for (int nt = 0; nt < 16; nt++) {
            m0 = fmaxf(m0, fmaxf(Cs[nt][0], Cs[nt][1]));
            m1 = fmaxf(m1, fmaxf(Cs[nt][2], Cs[nt][3]));
        }
        m0 = fmaxf(m0, __shfl_xor_sync(0xffffffffu, m0, 1));
        m0 = fmaxf(m0, __shfl_xor_sync(0xffffffffu, m0, 2));
        m1 = fmaxf(m1, __shfl_xor_sync(0xffffffffu, m1, 1));
        m1 = fmaxf(m1, __shfl_xor_sync(0xffffffffu, m1, 2));
        float s0 = 0.f, s1 = 0.f;
        #pragma unroll
        for (int nt = 0; nt < 16; nt++) {
            Cs[nt][0] = __expf(Cs[nt][0] - m0); Cs[nt][1] = __expf(Cs[nt][1] - m0);
            Cs[nt][2] = __expf(Cs[nt][2] - m1); Cs[nt][3] = __expf(Cs[nt][3] - m1);
            s0 += Cs[nt][0] + Cs[nt][1];
            s1 += Cs[nt][2] + Cs[nt][3];
        }
        s0 += __shfl_xor_sync(0xffffffffu, s0, 1);
        s0 += __shfl_xor_sync(0xffffffffu, s0, 2);
        s1 += __shfl_xor_sync(0xffffffffu, s1, 1);
        s1 += __shfl_xor_sync(0xffffffffu, s1, 2);
        const float i0 = 1.f / s0, i1 = 1.f / s1;
        #pragma unroll
        for (int nt = 0; nt < 16; nt++) {
            Cs[nt][0] *= i0; Cs[nt][1] *= i0; Cs[nt][2] *= i1; Cs[nt][3] *= i1;
        }
    }

    // repack attn into A-fragments (hi/lo)
    uint32_t ah[8][4], al[8][4];
    #pragma unroll
    for (int kt = 0; kt < 8; kt++) {
        ah[kt][0] = pack_hi(Cs[2*kt][0],   Cs[2*kt][1]);
        ah[kt][1] = pack_hi(Cs[2*kt][2],   Cs[2*kt][3]);
        ah[kt][2] = pack_hi(Cs[2*kt+1][0], Cs[2*kt+1][1]);
        ah[kt][3] = pack_hi(Cs[2*kt+1][2], Cs[2*kt+1][3]);
        al[kt][0] = pack_lo(Cs[2*kt][0],   Cs[2*kt][1]);
        al[kt][1] = pack_lo(Cs[2*kt][2],   Cs[2*kt][3]);
        al[kt][2] = pack_lo(Cs[2*kt+1][0], Cs[2*kt+1][1]);
        al[kt][3] = pack_lo(Cs[2*kt+1][2], Cs[2*kt+1][3]);
    }

    // ---------------- 8 output-column chunks of 32 ----------------
    for (int c = 0; c < 8; c++) {
        const unsigned buf = (c & 1) ? WB1 : WB0;
        CP_WAIT0();
        __syncthreads();   // chunk weights ready; prev-iter VT reads done
        if (c < 7) {
            unsigned dst = (c & 1) ? WB0 : WB1;
            const unsigned char* src = g_wimg + (unsigned)(c + 3) * WCHUNK;
            for (int i = t; i < WCHUNK / 16; i += NTHR) cp16(sm + dst + i * 16, src + i * 16);
            CP_COMMIT();
        }

        // V chunk = X @ Wv[:, c*32 .. c*32+31]
        float Cv[4][4];
        #pragma unroll
        for (int n = 0; n < 4; n++) { Cv[n][0] = Cv[n][1] = Cv[n][2] = Cv[n][3] = 0.f; }
        #pragma unroll 4
        for (int kt = 0; kt < 16; kt++) {
            unsigned ko = kt * 32 + q * 8;
            uint2 ah0 = *(const uint2*)(XH0 + ko), ah1 = *(const uint2*)(XH1 + ko);
            uint2 al0 = *(const uint2*)(XL0 + ko), al1 = *(const uint2*)(XL1 + ko);
            #pragma unroll
            for (int nt = 0; nt < 4; nt++) {
                const unsigned char* B = sm + buf + (unsigned)(nt * 8 + lq) * XSTR + ko;
                mma3(Cv[nt], ah0, ah1, al0, al1, *(const uint2*)B, *(const uint2*)(B + WLO));
            }
        }
        // transpose-store V chunk into VT image (hi/lo), tokens along k (permuted)
        {
            int p0 = kslot(R + lq) * 2, p1 = kslot(R + lq + 8) * 2;
            #pragma unroll
            for (int nt = 0; nt < 4; nt++) {
                int cc = nt * 8 + 2 * q;
                float v0 = Cv[nt][0], v1 = Cv[nt][1], v2 = Cv[nt][2], v3 = Cv[nt][3];
                float h0 = __bfloat162float(__float2bfloat16(v0));
                float h1 = __bfloat162float(__float2bfloat16(v1));
                float h2 = __bfloat162float(__float2bfloat16(v2));
                float h3 = __bfloat162float(__float2bfloat16(v3));
                *(__nv_bfloat16*)(sm + VTH_OFF + (cc)     * VSTR + p0) = __float2bfloat16(h0);
                *(__nv_bfloat16*)(sm + VTH_OFF + (cc + 1) * VSTR + p0) = __float2bfloat16(h1);
                *(__nv_bfloat16*)(sm + VTH_OFF + (cc)     * VSTR + p1) = __float2bfloat16(h2);
                *(__nv_bfloat16*)(sm + VTH_OFF + (cc + 1) * VSTR + p1) = __float2bfloat16(h3);
                *(__nv_bfloat16*)(sm + VTL_OFF + (cc)     * VSTR + p0) = __float2bfloat16(v0 - h0);
                *(__nv_bfloat16*)(sm + VTL_OFF + (cc + 1) * VSTR + p0) = __float2bfloat16(v1 - h1);
                *(__nv_bfloat16*)(sm + VTL_OFF + (cc)     * VSTR + p1) = __float2bfloat16(v2 - h2);
                *(__nv_bfloat16*)(sm + VTL_OFF + (cc + 1) * VSTR + p1) = __float2bfloat16(v3 - h3);
            }
        }
        __syncthreads();

        // O chunk = attn @ V
        float Co[4][4];
        #pragma unroll
        for (int n = 0; n < 4; n++) { Co[n][0] = Co[n][1] = Co[n][2] = Co[n][3] = 0.f; }
        #pragma unroll
        for (int nt = 0; nt < 4; nt++) {
            const unsigned char* Vp = sm + VTH_OFF + (unsigned)(nt * 8 + lq) * VSTR;
            #pragma unroll
            for (int kt = 0; kt < 8; kt++) {
                unsigned ko = kt * 32 + q * 8;
                uint2 bh = *(const uint2*)(Vp + ko);
                uint2 bl = *(const uint2*)(Vp + (VTL_OFF - VTH_OFF) + ko);
                mma16816(Co[nt], ah[kt][0], ah[kt][1], ah[kt][2], ah[kt][3], bh.x, bh.y);
                mma16816(Co[nt], ah[kt][0], ah[kt][1], ah[kt][2], ah[kt][3], bl.x, bl.y);
                mma16816(Co[nt], al[kt][0], al[kt][1], al[kt][2], al[kt][3], bh.x, bh.y);
            }
        }
        // epilogue: +bv, store (softmax rows sum to 1 -> bias adds directly)
        #pragma unroll
        for (int nt = 0; nt < 4; nt++) {
            int col = c * 32 + nt * 8 + 2 * q;
            float2 bb = *(const float2*)(bv + col);
            float2 o0 = make_float2(Co[nt][0] + bb.x, Co[nt][1] + bb.y);
            float2 o1 = make_float2(Co[nt][2] + bb.x, Co[nt][3] + bb.y);
            *(float2*)(Og + (long long)(R + lq) * 256 + col) = o0;
            *(float2*)(Og + (long long)(R + lq + 8) * 256 + col) = o1;
        }
    }
}

extern "C" void kernel_launch(void* const* d_in, const int* in_sizes, int n_in,
                              void* d_out, int out_size) {
    const float* X  = (const float*)d_in[0];
    const float* Wq = (const float*)d_in[1];
    const float* bq = (const float*)d_in[2];
    const float* Wk = (const float*)d_in[3];
    const float* bk = (const float*)d_in[4];
    const float* Wv = (const float*)d_in[5];
    const float* bv = (const float*)d_in[6];
    float* out = (float*)d_out;

    const int groups = in_sizes[0] / (128 * 256);   // 2048

    prep_weights<<<320, 256>>>(Wq, Wk, Wv);

    cudaFuncSetAttribute(attn_mma_kernel,
                         cudaFuncAttributeMaxDynamicSharedMemorySize, SMEM_BYTES);
    attn_mma_kernel<<<groups, NTHR, SMEM_BYTES>>>(X, bq, bk, bv, out);
}

// round 5
// speedup vs baseline: 3.7317x; 1.0105x over previous
#include <cuda_runtime.h>
#include <cuda_bf16.h>
#include <cstdint>

// B=16,H=128 -> 2048 groups; per group X[128,256], D=32.
#define NTHR 256

// ---------------- SMEM layout (bytes) ----------------
#define XSTR    544                  // X row stride (272 bf16 slots)
#define XH_OFF  0                    // X hi [128][XSTR]  = 69,632
#define XL_OFF  69632                // X lo
#define WB0     139264               // weight buffer 0 (34,816)
#define WB1     174080               // weight buffer 1 (34,816)
#define WCHUNK  34816                // chunk image: hi[32][XSTR] + lo[32][XSTR]
#define WLO     17408
#define KH_OFF  174080               // K image hi [128][KSTR] (overlays WB1)
#define KL_OFF  186368               // K image lo
#define KSTR    96
#define VTH_OFF 208896               // V^T chunk hi [32][VSTR]
#define VTL_OFF 218368               // V^T chunk lo
#define VSTR    296
#define SMEM_BYTES 227840

// k-permutation: within each 16-block, pairs (2q,2q+1) and (2q+8,2q+9) are
// contiguous -> one LDS.64 yields a full half A-fragment / B-fragment.
__device__ __forceinline__ int kslot(int k) {
    return (k & ~15) | (((k >> 1) & 3) << 2) | (((k >> 3) & 1) << 1) | (k & 1);
}

// 10 weight-chunk images: 0=Wq, 1=Wk, 2..9=Wv col-chunks of 32 (each [n=32][k=256])
__device__ __align__(16) unsigned char g_wimg[10 * WCHUNK];

// ---------------- helpers ----------------
__device__ __forceinline__ uint32_t smem_u32(const void* p) {
    uint32_t a;
    asm("{ .reg .u64 t; cvta.to.shared.u64 t, %1; cvt.u32.u64 %0, t; }" : "=r"(a) : "l"(p));
    return a;
}
__device__ __forceinline__ void cp16(void* sdst, const void* gsrc) {
    asm volatile("cp.async.cg.shared.global [%0], [%1], 16;"
                 :: "r"(smem_u32(sdst)), "l"(gsrc));
}
#define CP_COMMIT() asm volatile("cp.async.commit_group;" ::: "memory")
#define CP_WAIT0()  asm volatile("cp.async.wait_group 0;" ::: "memory")

__device__ __forceinline__ void mma16816(float* c, uint32_t a0, uint32_t a1,
                                         uint32_t a2, uint32_t a3,
                                         uint32_t b0, uint32_t b1) {
    asm volatile(
        "mma.sync.aligned.m16n8k16.row.col.f32.bf16.bf16.f32 "
        "{%0,%1,%2,%3},{%4,%5,%6,%7},{%8,%9},{%0,%1,%2,%3};"
        : "+f"(c[0]), "+f"(c[1]), "+f"(c[2]), "+f"(c[3])
        : "r"(a0), "r"(a1), "r"(a2), "r"(a3), "r"(b0), "r"(b1));
}
// 3-pass split: C += Ah*Bh + Ah*Bl + Al*Bh
__device__ __forceinline__ void mma3(float* c, uint2 ah0, uint2 ah1,
                                     uint2 al0, uint2 al1, uint2 bh, uint2 bl) {
    mma16816(c, ah0.x, ah1.x, ah0.y, ah1.y, bh.x, bh.y);
    mma16816(c, ah0.x, ah1.x, ah0.y, ah1.y, bl.x, bl.y);
    mma16816(c, al0.x, al1.x, al0.y, al1.y, bh.x, bh.y);
}

__device__ __forceinline__ uint32_t pack_hi(float x, float y) {
    __nv_bfloat162 p = __floats2bfloat162_rn(x, y);
    return *reinterpret_cast<uint32_t*>(&p);
}
__device__ __forceinline__ uint32_t pack_lo(float x, float y) {
    float xh = __bfloat162float(__float2bfloat16(x));
    float yh = __bfloat162float(__float2bfloat16(y));
    __nv_bfloat162 p = __floats2bfloat162_rn(x - xh, y - yh);
    return *reinterpret_cast<uint32_t*>(&p);
}

// =============== prep: weights -> bf16 hi/lo SMEM-image chunks ===============
__global__ void prep_weights(const float* __restrict__ Wq, const float* __restrict__ Wk,
                             const float* __restrict__ Wv) {
    int idx = blockIdx.x * 256 + threadIdx.x;   // 10*32*256 = 81920
    int chunk = idx >> 13;
    int n = (idx >> 8) & 31;
    int k = idx & 255;
    float w;
    if (chunk == 0)      w = Wq[k * 32 + n];
    else if (chunk == 1) w = Wk[k * 32 + n];
    else                 w = Wv[k * 256 + (chunk - 2) * 32 + n];
    __nv_bfloat16 h = __float2bfloat16(w);
    __nv_bfloat16 l = __float2bfloat16(w - __bfloat162float(h));
    unsigned off = (unsigned)chunk * WCHUNK + (unsigned)n * XSTR + (unsigned)kslot(k) * 2;
    *(__nv_bfloat16*)(g_wimg + off)       = h;
    *(__nv_bfloat16*)(g_wimg + off + WLO) = l;
}

// =============== main: one CTA per (b,h) group ===============
__global__ __launch_bounds__(NTHR, 1)
void attn_mma_kernel(const float* __restrict__ X,
                     const float* __restrict__ bq, const float* __restrict__ bk,
                     const float* __restrict__ bv, float* __restrict__ out) {
    extern __shared__ unsigned char sm[];
    const int t = threadIdx.x, w = t >> 5, lane = t & 31;
    const int q = lane & 3, lq = lane >> 2;
    const int R = w * 16;
    const long long g = blockIdx.x;
    const float* Xg = X + g * 32768LL;
    float* Og = out + g * 32768LL;

    // prefetch Wq -> WB0, Wk -> WB1
    for (int i = t; i < WCHUNK / 16; i += NTHR) cp16(sm + WB0 + i * 16, g_wimg + i * 16);
    for (int i = t; i < WCHUNK / 16; i += NTHR) cp16(sm + WB1 + i * 16, g_wimg + WCHUNK + i * 16);
    CP_COMMIT();

    // X load + bf16 hi/lo split into permuted layout
    {
        const float4* X4 = (const float4*)Xg;
        for (int i = t; i < 8192; i += NTHR) {
            int row = i >> 6, k0 = (i & 63) * 4;
            float4 f = X4[i];
            int s0 = kslot(k0), s1 = kslot(k0 + 2);
            unsigned b = (unsigned)row * XSTR;
            *(uint32_t*)(sm + XH_OFF + b + s0 * 2) = pack_hi(f.x, f.y);
            *(uint32_t*)(sm + XH_OFF + b + s1 * 2) = pack_hi(f.z, f.w);
            *(uint32_t*)(sm + XL_OFF + b + s0 * 2) = pack_lo(f.x, f.y);
            *(uint32_t*)(sm + XL_OFF + b + s1 * 2) = pack_lo(f.z, f.w);
        }
    }
    CP_WAIT0();
    __syncthreads();

    const unsigned char* XH0 = sm + XH_OFF + (unsigned)(R + lq) * XSTR;
    const unsigned char* XH1 = XH0 + 8 * XSTR;
    const unsigned char* XL0 = sm + XL_OFF + (unsigned)(R + lq) * XSTR;
    const unsigned char* XL1 = XL0 + 8 * XSTR;

    // ---------------- fused Q + K projection (A-frags loaded once) ----------------
    float Cq[4][4], Ck[4][4];
    #pragma unroll
    for (int n = 0; n < 4; n++) {
        Cq[n][0] = Cq[n][1] = Cq[n][2] = Cq[n][3] = 0.f;
        Ck[n][0] = Ck[n][1] = Ck[n][2] = Ck[n][3] = 0.f;
    }
    #pragma unroll 4
    for (int kt = 0; kt < 16; kt++) {
        unsigned ko = kt * 32 + q * 8;
        uint2 ah0 = *(const uint2*)(XH0 + ko), ah1 = *(const uint2*)(XH1 + ko);
        uint2 al0 = *(const uint2*)(XL0 + ko), al1 = *(const uint2*)(XL1 + ko);
        #pragma unroll
        for (int nt = 0; nt < 4; nt++) {
            const unsigned char* Bq = sm + WB0 + (unsigned)(nt * 8 + lq) * XSTR + ko;
            const unsigned char* Bk = sm + WB1 + (unsigned)(nt * 8 + lq) * XSTR + ko;
            mma3(Cq[nt], ah0, ah1, al0, al1, *(const uint2*)Bq, *(const uint2*)(Bq + WLO));
            mma3(Ck[nt], ah0, ah1, al0, al1, *(const uint2*)Bk, *(const uint2*)(Bk + WLO));
        }
    }
    // +bq, repack into scores A-fragments
    uint32_t qh[2][4], ql[2][4];
    #pragma unroll
    for (int nt = 0; nt < 4; nt++) {
        float2 bb = *(const float2*)(bq + nt * 8 + 2 * q);
        Cq[nt][0] += bb.x; Cq[nt][1] += bb.y; Cq[nt][2] += bb.x; Cq[nt][3] += bb.y;
    }
    #pragma unroll
    for (int kt = 0; kt < 2; kt++) {
        qh[kt][0] = pack_hi(Cq[2*kt][0],   Cq[2*kt][1]);
        qh[kt][1] = pack_hi(Cq[2*kt][2],   Cq[2*kt][3]);
        qh[kt][2] = pack_hi(Cq[2*kt+1][0], Cq[2*kt+1][1]);
        qh[kt][3] = pack_hi(Cq[2*kt+1][2], Cq[2*kt+1][3]);
        ql[kt][0] = pack_lo(Cq[2*kt][0],   Cq[2*kt][1]);
        ql[kt][1] = pack_lo(Cq[2*kt][2],   Cq[2*kt][3]);
        ql[kt][2] = pack_lo(Cq[2*kt+1][0], Cq[2*kt+1][1]);
        ql[kt][3] = pack_lo(Cq[2*kt+1][2], Cq[2*kt+1][3]);
    }
    __syncthreads();   // all warps done reading WB0/WB1 as weights

    // prefetch Wv chunk 0 -> WB0 (overlaps K-image write + scores)
    for (int i = t; i < WCHUNK / 16; i += NTHR) cp16(sm + WB0 + i * 16, g_wimg + 2 * WCHUNK + i * 16);
    CP_COMMIT();

    // write K image (+bk) into WB1 region, split hi/lo
    #pragma unroll
    for (int nt = 0; nt < 4; nt++) {
        float2 bb = *(const float2*)(bk + nt * 8 + 2 * q);
        float c0 = Ck[nt][0] + bb.x, c1 = Ck[nt][1] + bb.y;
        float c2 = Ck[nt][2] + bb.x, c3 = Ck[nt][3] + bb.y;
        int p = kslot(nt * 8 + 2 * q) * 2;
        unsigned o0 = (unsigned)(R + lq) * KSTR + p;
        unsigned o1 = (unsigned)(R + lq + 8) * KSTR + p;
        *(uint32_t*)(sm + KH_OFF + o0) = pack_hi(c0, c1);
        *(uint32_t*)(sm + KH_OFF + o1) = pack_hi(c2, c3);
        *(uint32_t*)(sm + KL_OFF + o0) = pack_lo(c0, c1);
        *(uint32_t*)(sm + KL_OFF + o1) = pack_lo(c2, c3);
    }
    __syncthreads();

    // ---------------- scores S = Q @ K^T (nt-groups of 4 for ILP) ----------------
    float Cs[16][4];
    #pragma unroll
    for (int n = 0; n < 16; n++) { Cs[n][0] = Cs[n][1] = Cs[n][2] = Cs[n][3] = 0.f; }
    #pragma unroll
    for (int ng = 0; ng < 4; ng++) {
        #pragma unroll
        for (int kt = 0; kt < 2; kt++) {
            unsigned ko = kt * 32 + q * 8;
            #pragma unroll
            for (int ni = 0; ni < 4; ni++) {
                int nt = ng * 4 + ni;
                const unsigned char* Kp = sm + KH_OFF + (unsigned)(nt * 8 + lq) * KSTR + ko;
                uint2 bh = *(const uint2*)Kp;
                uint2 bl = *(const uint2*)(Kp + (KL_OFF - KH_OFF));
                mma16816(Cs[nt], qh[kt][0], qh[kt][1], qh[kt][2], qh[kt][3], bh.x, bh.y);
                mma16816(Cs[nt], qh[kt][0], qh[kt][1], qh[kt][2], qh[kt][3], bl.x, bl.y);
                mma16816(Cs[nt], ql[kt][0], ql[kt][1], ql[kt][2], ql[kt][3], bh.x, bh.y);
            }
        }
    }

    // ---------------- softmax (registers + quad shuffles) ----------------
    {
        float m0 = -1e30f, m1 = -1e30f;
        #pragma unroll
        for (int nt = 0; nt < 16; nt++) {
            m0 = fmaxf(m0, fmaxf(Cs[nt][0], Cs[nt][1]));
            m1 = fmaxf(m1, fmaxf(Cs[nt][2], Cs[nt][3]));
        }
        m0 = fmaxf(m0, __shfl_xor_sync(0xffffffffu, m0, 1));
        m0 = fmaxf(m0, __shfl_xor_sync(0xffffffffu, m0, 2));
        m1 = fmaxf(m1, __shfl_xor_sync(0xffffffffu, m1, 1));
        m1 = fmaxf(m1, __shfl_xor_sync(0xffffffffu, m1, 2));
        float s0 = 0.f, s1 = 0.f;
        #pragma unroll
        for (int nt = 0; nt < 16; nt++) {
            Cs[nt][0] = __expf(Cs[nt][0] - m0); Cs[nt][1] = __expf(Cs[nt][1] - m0);
            Cs[nt][2] = __expf(Cs[nt][2] - m1); Cs[nt][3] = __expf(Cs[nt][3] - m1);
            s0 += Cs[nt][0] + Cs[nt][1];
            s1 += Cs[nt][2] + Cs[nt][3];
        }
        s0 += __shfl_xor_sync(0xffffffffu, s0, 1);
        s0 += __shfl_xor_sync(0xffffffffu, s0, 2);
        s1 += __shfl_xor_sync(0xffffffffu, s1, 1);
        s1 += __shfl_xor_sync(0xffffffffu, s1, 2);
        const float i0 = 1.f / s0, i1 = 1.f / s1;
        #pragma unroll
        for (int nt = 0; nt < 16; nt++) {
            Cs[nt][0] *= i0; Cs[nt][1] *= i0; Cs[nt][2] *= i1; Cs[nt][3] *= i1;
        }
    }

    // repack attn into A-fragments (hi/lo)
    uint32_t ah[8][4], al[8][4];
    #pragma unroll
    for (int kt = 0; kt < 8; kt++) {
        ah[kt][0] = pack_hi(Cs[2*kt][0],   Cs[2*kt][1]);
        ah[kt][1] = pack_hi(Cs[2*kt][2],   Cs[2*kt][3]);
        ah[kt][2] = pack_hi(Cs[2*kt+1][0], Cs[2*kt+1][1]);
        ah[kt][3] = pack_hi(Cs[2*kt+1][2], Cs[2*kt+1][3]);
        al[kt][0] = pack_lo(Cs[2*kt][0],   Cs[2*kt][1]);
        al[kt][1] = pack_lo(Cs[2*kt][2],   Cs[2*kt][3]);
        al[kt][2] = pack_lo(Cs[2*kt+1][0], Cs[2*kt+1][1]);
        al[kt][3] = pack_lo(Cs[2*kt+1][2], Cs[2*kt+1][3]);
    }

    // precomputed V-transpose constants
    const int j2 = 2 * (lq >> 1);
    const int pA = kslot(R + j2) * 2;        // token pair (R+j2, R+j2+1)
    const int pB = kslot(R + j2 + 8) * 2;    // token pair (R+j2+8, R+j2+9)
    const bool oddlq = (lq & 1);

    // ---------------- 8 output-column chunks of 32 ----------------
    for (int c = 0; c < 8; c++) {
        const unsigned buf = (c & 1) ? WB1 : WB0;
        CP_WAIT0();
        __syncthreads();   // chunk weights ready; prev-iter VT reads done
        if (c < 7) {
            unsigned dst = (c & 1) ? WB0 : WB1;
            const unsigned char* src = g_wimg + (unsigned)(c + 3) * WCHUNK;
            for (int i = t; i < WCHUNK / 16; i += NTHR) cp16(sm + dst + i * 16, src + i * 16);
            CP_COMMIT();
        }

        // V chunk = X @ Wv[:, c*32 .. c*32+31]
        float Cv[4][4];
        #pragma unroll
        for (int n = 0; n < 4; n++) { Cv[n][0] = Cv[n][1] = Cv[n][2] = Cv[n][3] = 0.f; }
        #pragma unroll 4
        for (int kt = 0; kt < 16; kt++) {
            unsigned ko = kt * 32 + q * 8;
            uint2 ah0 = *(const uint2*)(XH0 + ko), ah1 = *(const uint2*)(XH1 + ko);
            uint2 al0 = *(const uint2*)(XL0 + ko), al1 = *(const uint2*)(XL1 + ko);
            #pragma unroll
            for (int nt = 0; nt < 4; nt++) {
                const unsigned char* B = sm + buf + (unsigned)(nt * 8 + lq) * XSTR + ko;
                mma3(Cv[nt], ah0, ah1, al0, al1, *(const uint2*)B, *(const uint2*)(B + WLO));
            }
        }
        // transpose-store V chunk: shfl.xor(4) exchanges token-adjacent values,
        // pack bf16 pairs -> STS.32 into VT image (hi/lo)
        #pragma unroll
        for (int nt = 0; nt < 4; nt++) {
            float v0 = Cv[nt][0], v1 = Cv[nt][1], v2 = Cv[nt][2], v3 = Cv[nt][3];
            float sendA = oddlq ? v0 : v1;
            float recvA = __shfl_xor_sync(0xffffffffu, sendA, 4);
            float sendB = oddlq ? v2 : v3;
            float recvB = __shfl_xor_sync(0xffffffffu, sendB, 4);
            float a0 = oddlq ? recvA : v0, a1 = oddlq ? v1 : recvA;
            float b0 = oddlq ? recvB : v2, b1 = oddlq ? v3 : recvB;
            unsigned cc = (unsigned)(nt * 8 + 2 * q + (oddlq ? 1 : 0)) * VSTR;
            *(uint32_t*)(sm + VTH_OFF + cc + pA) = pack_hi(a0, a1);
            *(uint32_t*)(sm + VTH_OFF + cc + pB) = pack_hi(b0, b1);
            *(uint32_t*)(sm + VTL_OFF + cc + pA) = pack_lo(a0, a1);
            *(uint32_t*)(sm + VTL_OFF + cc + pB) = pack_lo(b0, b1);
        }
        __syncthreads();

        // O chunk = attn @ V  (kt outer, nt inner -> 4 independent chains)
        float Co[4][4];
        #pragma unroll
        for (int n = 0; n < 4; n++) { Co[n][0] = Co[n][1] = Co[n][2] = Co[n][3] = 0.f; }
        #pragma unroll
        for (int kt = 0; kt < 8; kt++) {
            unsigned ko = kt * 32 + q * 8;
            #pragma unroll
            for (int nt = 0; nt < 4; nt++) {
                const unsigned char* Vp = sm + VTH_OFF + (unsigned)(nt * 8 + lq) * VSTR + ko;
                uint2 bh = *(const uint2*)Vp;
                uint2 bl = *(const uint2*)(Vp + (VTL_OFF - VTH_OFF));
                mma16816(Co[nt], ah[kt][0], ah[kt][1], ah[kt][2], ah[kt][3], bh.x, bh.y);
                mma16816(Co[nt], ah[kt][0], ah[kt][1], ah[kt][2], ah[kt][3], bl.x, bl.y);
                mma16816(Co[nt], al[kt][0], al[kt][1], al[kt][2], al[kt][3], bh.x, bh.y);
            }
        }
        // epilogue: +bv, store (softmax rows sum to 1 -> bias adds directly)
        #pragma unroll
        for (int nt = 0; nt < 4; nt++) {
            int col = c * 32 + nt * 8 + 2 * q;
            float2 bb = *(const float2*)(bv + col);
            float2 o0 = make_float2(Co[nt][0] + bb.x, Co[nt][1] + bb.y);
            float2 o1 = make_float2(Co[nt][2] + bb.x, Co[nt][3] + bb.y);
            *(float2*)(Og + (long long)(R + lq) * 256 + col) = o0;
            *(float2*)(Og + (long long)(R + lq + 8) * 256 + col) = o1;
        }
    }
}

extern "C" void kernel_launch(void* const* d_in, const int* in_sizes, int n_in,
                              void* d_out, int out_size) {
    const float* X  = (const float*)d_in[0];
    const float* Wq = (const float*)d_in[1];
    const float* bq = (const float*)d_in[2];
    const float* Wk = (const float*)d_in[3];
    const float* bk = (const float*)d_in[4];
    const float* Wv = (const float*)d_in[5];
    const float* bv = (const float*)d_in[6];
    float* out = (float*)d_out;

    const int groups = in_sizes[0] / (128 * 256);   // 2048

    prep_weights<<<320, 256>>>(Wq, Wk, Wv);

    cudaFuncSetAttribute(attn_mma_kernel,
                         cudaFuncAttributeMaxDynamicSharedMemorySize, SMEM_BYTES);
    attn_mma_kernel<<<groups, NTHR, SMEM_BYTES>>>(X, bq, bk, bv, out);
}